// round 15
// baseline (speedup 1.0000x reference)
#include <cuda_runtime.h>
#include <cuda_fp16.h>
#include <cstdint>

// h (projected features) stored naturally [b][j][f] as fp16.
__device__ __align__(16) __half g_h_hi[4 * 2048 * 128];
__device__ float g_s[4 * 2048];

static __device__ __forceinline__ uint32_t smem_u32(const void* p) {
    uint32_t a;
    asm("{ .reg .u64 t; cvta.to.shared.u64 t, %1; cvt.u32.u64 %0, t; }" : "=r"(a) : "l"(p));
    return a;
}
static __device__ __forceinline__ void cp16(uint32_t dst, const void* src) {
    asm volatile("cp.async.cg.shared.global [%0], [%1], 16;" :: "r"(dst), "l"(src) : "memory");
}
static __device__ __forceinline__ void cp_commit() {
    asm volatile("cp.async.commit_group;" ::: "memory");
}
template <int N> static __device__ __forceinline__ void cp_waitg() {
    asm volatile("cp.async.wait_group %0;" :: "n"(N) : "memory");
}
static __device__ __forceinline__ void ldsm4(uint32_t* r, uint32_t a) {
    asm volatile("ldmatrix.sync.aligned.m8n8.x4.shared.b16 {%0,%1,%2,%3}, [%4];"
                 : "=r"(r[0]), "=r"(r[1]), "=r"(r[2]), "=r"(r[3]) : "r"(a));
}
static __device__ __forceinline__ void ldsm4t(uint32_t* r, uint32_t a) {
    asm volatile("ldmatrix.sync.aligned.m8n8.x4.trans.shared.b16 {%0,%1,%2,%3}, [%4];"
                 : "=r"(r[0]), "=r"(r[1]), "=r"(r[2]), "=r"(r[3]) : "r"(a));
}
static __device__ __forceinline__ void mma16816(float* c, const uint32_t* a,
                                                uint32_t b0, uint32_t b1) {
    asm volatile(
        "mma.sync.aligned.m16n8k16.row.col.f32.f16.f16.f32 "
        "{%0,%1,%2,%3}, {%4,%5,%6,%7}, {%8,%9}, {%0,%1,%2,%3};"
        : "+f"(c[0]), "+f"(c[1]), "+f"(c[2]), "+f"(c[3])
        : "r"(a[0]), "r"(a[1]), "r"(a[2]), "r"(a[3]), "r"(b0), "r"(b1));
}
static __device__ __forceinline__ float leaky(float x) {
    return fmaxf(x, 0.f) + 0.2f * fminf(x, 0.f);
}

// ---------------- K1: h = x@W via fp16 hi/lo 3-pass HMMA, s = h@a_w + ab ---
static constexpr int XP       = 272;
static constexpr int OFF_XHI  = 0;
static constexpr int OFF_XLO  = OFF_XHI + 64 * XP;
static constexpr int OFF_WHI  = OFF_XLO + 64 * XP;
static constexpr int OFF_WLO  = OFF_WHI + 128 * XP;
static constexpr int OFF_AW   = OFF_WLO + 128 * XP;
static constexpr int OFF_SSM  = OFF_AW + 512;
static constexpr int SM1_SIZE = OFF_SSM + 256;

__global__ void __launch_bounds__(256) k_prep(const float* __restrict__ x,
                                              const float* __restrict__ W,
                                              const float* __restrict__ aw,
                                              const float* __restrict__ ab) {
    extern __shared__ char smp[];
    const uint32_t sbp = smem_u32(smp);
    const int tid = threadIdx.x, wid = tid >> 5, lane = tid & 31;
    const int b = blockIdx.x >> 5;
    const int i0 = (blockIdx.x & 31) * 64;

    const float4* xb = (const float4*)(x + ((size_t)b * 2048 + i0) * 128);
#pragma unroll
    for (int k = 0; k < 8; k++) {
        int idx = tid + 256 * k;
        int row = idx >> 5, c4 = idx & 31;
        float4 v = xb[idx];
        __half2 h0 = __floats2half2_rn(v.x, v.y);
        __half2 h1 = __floats2half2_rn(v.z, v.w);
        float2 f0 = __half22float2(h0), f1 = __half22float2(h1);
        __half2 l0 = __floats2half2_rn(v.x - f0.x, v.y - f0.y);
        __half2 l1 = __floats2half2_rn(v.z - f1.x, v.w - f1.y);
        char* d = smp + OFF_XHI + row * XP + c4 * 8;
        *(uint2*)d = make_uint2(*(uint32_t*)&h0, *(uint32_t*)&h1);
        *(uint2*)(d + (OFF_XLO - OFF_XHI)) = make_uint2(*(uint32_t*)&l0, *(uint32_t*)&l1);
    }
    const float4* wb = (const float4*)W;
#pragma unroll
    for (int k = 0; k < 16; k++) {
        int idx = tid + 256 * k;
        int row = idx >> 5, c4 = idx & 31;
        float4 v = wb[idx];
        __half2 h0 = __floats2half2_rn(v.x, v.y);
        __half2 h1 = __floats2half2_rn(v.z, v.w);
        float2 f0 = __half22float2(h0), f1 = __half22float2(h1);
        __half2 l0 = __floats2half2_rn(v.x - f0.x, v.y - f0.y);
        __half2 l1 = __floats2half2_rn(v.z - f1.x, v.w - f1.y);
        char* d = smp + OFF_WHI + row * XP + c4 * 8;
        *(uint2*)d = make_uint2(*(uint32_t*)&h0, *(uint32_t*)&h1);
        *(uint2*)(d + (OFF_WLO - OFF_WHI)) = make_uint2(*(uint32_t*)&l0, *(uint32_t*)&l1);
    }
    if (tid < 128) ((float*)(smp + OFF_AW))[tid] = aw[tid];
    if (tid < 64) ((float*)(smp + OFF_SSM))[tid] = 0.f;
    __syncthreads();

    const int r0 = (wid & 3) * 16, c0 = (wid >> 2) * 64;
    float acc[8][4];
#pragma unroll
    for (int nb = 0; nb < 8; nb++)
#pragma unroll
        for (int q = 0; q < 4; q++) acc[nb][q] = 0.f;

    const uint32_t arow = (uint32_t)((r0 + (lane & 15)) * XP + ((lane >> 4) << 4));
    const uint32_t brow = (uint32_t)((lane & 15) * XP + ((lane >> 4) << 4) + c0 * 2);
#pragma unroll
    for (int kk = 0; kk < 8; kk++) {
        uint32_t aph[4], apl[4];
        ldsm4(aph, sbp + OFF_XHI + arow + kk * 32);
        ldsm4(apl, sbp + OFF_XLO + arow + kk * 32);
        const uint32_t hb = sbp + OFF_WHI + brow + kk * 16 * XP;
#pragma unroll
        for (int n0 = 0; n0 < 4; n0++) {
            uint32_t bh[4], bl[4];
            ldsm4t(bh, hb + n0 * 32);
            ldsm4t(bl, hb + (OFF_WLO - OFF_WHI) + n0 * 32);
            mma16816(acc[2 * n0],     aph, bh[0], bh[1]);
            mma16816(acc[2 * n0 + 1], aph, bh[2], bh[3]);
            mma16816(acc[2 * n0],     apl, bh[0], bh[1]);
            mma16816(acc[2 * n0 + 1], apl, bh[2], bh[3]);
            mma16816(acc[2 * n0],     aph, bl[0], bl[1]);
            mma16816(acc[2 * n0 + 1], aph, bl[2], bl[3]);
        }
    }

    const float* awp = (const float*)(smp + OFF_AW);
    float* ssm = (float*)(smp + OFF_SSM);
    const int row_lo = r0 + (lane >> 2);
    __half* hout0 = g_h_hi + ((size_t)b * 2048 + i0 + row_lo) * 128;
    __half* hout1 = hout0 + 8 * 128;
    float s0 = 0.f, s1 = 0.f;
#pragma unroll
    for (int nb = 0; nb < 8; nb++) {
        const int col = c0 + nb * 8 + (lane & 3) * 2;
        __half2 o0 = __floats2half2_rn(acc[nb][0], acc[nb][1]);
        __half2 o1 = __floats2half2_rn(acc[nb][2], acc[nb][3]);
        *(uint32_t*)(hout0 + col) = *(uint32_t*)&o0;
        *(uint32_t*)(hout1 + col) = *(uint32_t*)&o1;
        s0 += acc[nb][0] * awp[col] + acc[nb][1] * awp[col + 1];
        s1 += acc[nb][2] * awp[col] + acc[nb][3] * awp[col + 1];
    }
    s0 += __shfl_xor_sync(0xffffffffu, s0, 1);
    s0 += __shfl_xor_sync(0xffffffffu, s0, 2);
    s1 += __shfl_xor_sync(0xffffffffu, s1, 1);
    s1 += __shfl_xor_sync(0xffffffffu, s1, 2);
    if ((lane & 3) == 0) {
        atomicAdd(&ssm[row_lo], s0);
        atomicAdd(&ssm[row_lo + 8], s1);
    }
    __syncthreads();
    if (tid < 64) g_s[b * 2048 + i0 + tid] = ssm[tid] + ab[0];
}

// ---------------- K2: lockstep pipeline, consumer retiled 2row x 4col ------
// 512 threads: warps 0-7 = MMA (2/SMSP), warps 8-15 = producers.
// Consumer warp w: rows (w&1)*32..+32, cols (w>>1)*32..+32
//   -> LDSM per chunk: 2 ldsm4 (P) + 2 ldsm4t (H) per kk = 16/warp (was 20).
// P: 2 stages [64][72]h (144B pitch). H: 4 stages [64][136]h (272B pitch).
static constexpr int P_PITCH = 144;
static constexpr int H_PITCH = 272;
static constexpr int P_ST    = 64 * P_PITCH;        // 9216
static constexpr int H_ST    = 64 * H_PITCH;        // 17408
static constexpr int OFF_P   = 0;                   // 2 stages -> 18432
static constexpr int OFF_H   = 2 * P_ST;            // 18432; 4 stages -> 69632
static constexpr int OFF_SS   = OFF_H + 4 * H_ST;   // 88064 (2048 f)
static constexpr int OFF_BIAS = OFF_SS + 8192;      // 96256 (128 f)
static constexpr int OFF_LS   = OFF_BIAS + 512;     // 96768 (64 f)
static constexpr int OFF_SMAX = OFF_LS + 256;       // 97024 (1 f)
static constexpr int SM2_SIZE = OFF_SMAX + 16;      // 97040

__global__ void __launch_bounds__(512) k_attn(const float* __restrict__ A,
                                              const float* __restrict__ bias,
                                              float* __restrict__ out) {
    extern __shared__ char sm[];
    const uint32_t sb = smem_u32(sm);
    const int tid = threadIdx.x, wid = tid >> 5, lane = tid & 31;
    const int b = blockIdx.x >> 5;
    const int i0 = (blockIdx.x & 31) << 6;

    const __half* Hhig = g_h_hi + (size_t)b * 2048 * 128;
    const int p = tid - 256;                 // producer index (valid when wid>=8)
    const int pfc = p & 15, pjrb = p >> 4;

    // preamble: producers issue H(0), H(1) before anything else
    if (wid >= 8) {
#pragma unroll
        for (int tc = 0; tc < 2; tc++) {
            const uint32_t bb = sb + OFF_H + tc * H_ST;
#pragma unroll
            for (int c = 0; c < 4; c++) {
                const int jr = pjrb + 16 * c;
                cp16(bb + jr * H_PITCH + pfc * 16,
                     Hhig + (size_t)(tc * 64 + jr) * 128 + pfc * 8);
            }
            cp_commit();
        }
    }

    float* ss = (float*)(sm + OFF_SS);
    {   // preload s for whole batch + bias
        const float4* sg = (const float4*)(g_s + b * 2048);
        ((float4*)ss)[tid] = sg[tid];
        if (tid < 128) ((float*)(sm + OFF_BIAS))[tid] = bias[tid];
    }
    __syncthreads();

    // batch-wide max of s (fp16-safe shift)
    {
        float mx = -1e30f;
#pragma unroll
        for (int k = 0; k < 4; k++) mx = fmaxf(mx, ss[tid + 512 * k]);
#pragma unroll
        for (int off = 16; off >= 1; off >>= 1)
            mx = fmaxf(mx, __shfl_xor_sync(0xffffffffu, mx, off));
        if (lane == 0) ((float*)(sm + OFF_LS))[wid] = mx;
    }
    __syncthreads();
    if (tid == 0) {
        float mx = -1e30f;
#pragma unroll
        for (int w = 0; w < 16; w++) mx = fmaxf(mx, ((float*)(sm + OFF_LS))[w]);
        *(float*)(sm + OFF_SMAX) = mx;
    }
    __syncthreads();
    const float smax = *(const float*)(sm + OFF_SMAX);

    // ---- per-role persistent state ----
    // producer
    const int rbase = p >> 4, cbase = (p & 15) * 4;
    const float* Abase = A + ((size_t)b * 2048 + i0) * 2048;
    float s_i[4], m_i[4], lsum[4];
    float4 av[4];
    // consumer: 2 row-groups x 4 col-groups
    const int r0 = (wid & 1) * 32, c0 = (wid >> 1) * 32;
    float acc[2][4][4];
    const uint32_t arow = (uint32_t)((r0 + (lane & 15)) * P_PITCH + ((lane >> 4) << 4));
    const uint32_t brow = (uint32_t)((lane & 15) * H_PITCH + ((lane >> 4) << 4) + c0 * 2);

    if (wid >= 8) {
#pragma unroll
        for (int it = 0; it < 4; it++) {
            s_i[it] = ss[i0 + rbase + 16 * it];
            m_i[it] = leaky(s_i[it] + smax);
            lsum[it] = 0.f;
        }
#pragma unroll
        for (int it = 0; it < 4; it++)
            av[it] = *(const float4*)(Abase + (size_t)(rbase + 16 * it) * 2048 + cbase);
    } else {
#pragma unroll
        for (int mt = 0; mt < 2; mt++)
#pragma unroll
            for (int nb = 0; nb < 4; nb++)
#pragma unroll
                for (int q = 0; q < 4; q++) acc[mt][nb][q] = 0.f;
    }

#pragma unroll 1
    for (int t = 0; t <= 32; t++) {
        if (wid >= 8) {
            if (t < 32) {
                // prefetch H(t+2)
                if (t < 30) {
                    const uint32_t bbn = sb + OFF_H + ((t + 2) & 3) * H_ST;
#pragma unroll
                    for (int c = 0; c < 4; c++) {
                        const int jr = pjrb + 16 * c;
                        cp16(bbn + jr * H_PITCH + pfc * 16,
                             Hhig + (size_t)((t + 2) * 64 + jr) * 128 + pfc * 8);
                    }
                    cp_commit();
                }
                // A prefetch t+1
                const int j0n = (t < 31) ? (t + 1) * 64 : t * 64;
                float4 avn[4];
#pragma unroll
                for (int it = 0; it < 4; it++)
                    avn[it] = *(const float4*)(Abase + (size_t)(rbase + 16 * it) * 2048 + j0n + cbase);

                // P(t) -> stage t&1
                const int j0 = t * 64;
                char* bp = sm + OFF_P + (t & 1) * P_ST;
                const float4 sv = *(const float4*)(ss + j0 + cbase);
#pragma unroll
                for (int it = 0; it < 4; it++) {
                    const float si = s_i[it], m = m_i[it];
                    float e0 = leaky(si + sv.x) - m;
                    float e1 = leaky(si + sv.y) - m;
                    float e2 = leaky(si + sv.z) - m;
                    float e3 = leaky(si + sv.w) - m;
                    float p0 = __expf(e0 + av[it].x), p1 = __expf(e1 + av[it].y);
                    float p2 = __expf(e2 + av[it].z), p3 = __expf(e3 + av[it].w);
                    lsum[it] += (p0 + p1) + (p2 + p3);
                    __half2 hA = __floats2half2_rn(p0, p1);
                    __half2 hB = __floats2half2_rn(p2, p3);
                    *(uint2*)(bp + (rbase + 16 * it) * P_PITCH + cbase * 2) =
                        make_uint2(*(uint32_t*)&hA, *(uint32_t*)&hB);
                }
#pragma unroll
                for (int it = 0; it < 4; it++) av[it] = avn[it];

                // H(t) must be complete before next iteration's consumers use it
                if (t < 30)       cp_waitg<2>();
                else if (t == 30) cp_waitg<1>();
                else              cp_waitg<0>();
            }
        } else {
            if (t >= 1) {
                const int c = t - 1;
                const uint32_t pb = sb + OFF_P + (c & 1) * P_ST;
                const uint32_t hb0 = sb + OFF_H + (c & 3) * H_ST;
#pragma unroll
                for (int kk = 0; kk < 4; kk++) {
                    uint32_t ap0[4], ap1[4];
                    ldsm4(ap0, pb + arow + kk * 32);
                    ldsm4(ap1, pb + arow + 16 * P_PITCH + kk * 32);
                    const uint32_t hb = hb0 + brow + kk * 16 * H_PITCH;
                    uint32_t bh0[4], bh1[4];
                    ldsm4t(bh0, hb);
                    ldsm4t(bh1, hb + 32);
                    mma16816(acc[0][0], ap0, bh0[0], bh0[1]);
                    mma16816(acc[0][1], ap0, bh0[2], bh0[3]);
                    mma16816(acc[0][2], ap0, bh1[0], bh1[1]);
                    mma16816(acc[0][3], ap0, bh1[2], bh1[3]);
                    mma16816(acc[1][0], ap1, bh0[0], bh0[1]);
                    mma16816(acc[1][1], ap1, bh0[2], bh0[3]);
                    mma16816(acc[1][2], ap1, bh1[0], bh1[1]);
                    mma16816(acc[1][3], ap1, bh1[2], bh1[3]);
                }
            }
        }
        __syncthreads();
    }

    // producers publish per-row sums
    if (wid >= 8) {
        float* ls = (float*)(sm + OFF_LS);
#pragma unroll
        for (int it = 0; it < 4; it++) {
            float v = lsum[it];
            v += __shfl_xor_sync(0xffffffffu, v, 1);
            v += __shfl_xor_sync(0xffffffffu, v, 2);
            v += __shfl_xor_sync(0xffffffffu, v, 4);
            v += __shfl_xor_sync(0xffffffffu, v, 8);
            if ((p & 15) == 0) ls[rbase + 16 * it] = v;
        }
    }
    __syncthreads();

    if (wid < 8) {
        const float* ls = (const float*)(sm + OFF_LS);
        const float* bs = (const float*)(sm + OFF_BIAS);
#pragma unroll
        for (int mt = 0; mt < 2; mt++) {
            const int row_lo = r0 + 16 * mt + (lane >> 2);
            const float linv0 = 1.0f / ls[row_lo];
            const float linv1 = 1.0f / ls[row_lo + 8];
            float* orow0 = out + ((size_t)b * 2048 + i0 + row_lo) * 128;
            float* orow1 = orow0 + 8 * 128;
#pragma unroll
            for (int nb = 0; nb < 4; nb++) {
                const int col = c0 + nb * 8 + (lane & 3) * 2;
                float2 o0 = make_float2(acc[mt][nb][0] * linv0 + bs[col],
                                        acc[mt][nb][1] * linv0 + bs[col + 1]);
                float2 o1 = make_float2(acc[mt][nb][2] * linv1 + bs[col],
                                        acc[mt][nb][3] * linv1 + bs[col + 1]);
                *(float2*)(orow0 + col) = o0;
                *(float2*)(orow1 + col) = o1;
            }
        }
    }
}

extern "C" void kernel_launch(void* const* d_in, const int* in_sizes, int n_in,
                              void* d_out, int out_size) {
    (void)in_sizes; (void)n_in; (void)out_size;
    const float* x    = (const float*)d_in[0];
    const float* A    = (const float*)d_in[1];
    const float* W    = (const float*)d_in[2];
    const float* aw   = (const float*)d_in[3];
    const float* ab   = (const float*)d_in[4];
    const float* bias = (const float*)d_in[5];
    float* out = (float*)d_out;

    cudaFuncSetAttribute(k_prep, cudaFuncAttributeMaxDynamicSharedMemorySize, SM1_SIZE);
    cudaFuncSetAttribute(k_attn, cudaFuncAttributeMaxDynamicSharedMemorySize, SM2_SIZE);

    k_prep<<<128, 256, SM1_SIZE>>>(x, W, aw, ab);
    k_attn<<<128, 512, SM2_SIZE>>>(A, bias, out);
}

// round 16
// speedup vs baseline: 1.6673x; 1.6673x over previous
#include <cuda_runtime.h>
#include <cuda_fp16.h>
#include <cstdint>

// h (projected features) stored naturally [b][j][f] as fp16.
__device__ __align__(16) __half g_h_hi[4 * 2048 * 128];
__device__ float g_s[4 * 2048];

static __device__ __forceinline__ uint32_t smem_u32(const void* p) {
    uint32_t a;
    asm("{ .reg .u64 t; cvta.to.shared.u64 t, %1; cvt.u32.u64 %0, t; }" : "=r"(a) : "l"(p));
    return a;
}
static __device__ __forceinline__ void cp16(uint32_t dst, const void* src) {
    asm volatile("cp.async.cg.shared.global [%0], [%1], 16;" :: "r"(dst), "l"(src) : "memory");
}
static __device__ __forceinline__ void cp_commit() {
    asm volatile("cp.async.commit_group;" ::: "memory");
}
template <int N> static __device__ __forceinline__ void cp_waitg() {
    asm volatile("cp.async.wait_group %0;" :: "n"(N) : "memory");
}
static __device__ __forceinline__ void ldsm4(uint32_t* r, uint32_t a) {
    asm volatile("ldmatrix.sync.aligned.m8n8.x4.shared.b16 {%0,%1,%2,%3}, [%4];"
                 : "=r"(r[0]), "=r"(r[1]), "=r"(r[2]), "=r"(r[3]) : "r"(a));
}
static __device__ __forceinline__ void ldsm4t(uint32_t* r, uint32_t a) {
    asm volatile("ldmatrix.sync.aligned.m8n8.x4.trans.shared.b16 {%0,%1,%2,%3}, [%4];"
                 : "=r"(r[0]), "=r"(r[1]), "=r"(r[2]), "=r"(r[3]) : "r"(a));
}
static __device__ __forceinline__ void mma16816(float* c, const uint32_t* a,
                                                uint32_t b0, uint32_t b1) {
    asm volatile(
        "mma.sync.aligned.m16n8k16.row.col.f32.f16.f16.f32 "
        "{%0,%1,%2,%3}, {%4,%5,%6,%7}, {%8,%9}, {%0,%1,%2,%3};"
        : "+f"(c[0]), "+f"(c[1]), "+f"(c[2]), "+f"(c[3])
        : "r"(a[0]), "r"(a[1]), "r"(a[2]), "r"(a[3]), "r"(b0), "r"(b1));
}
static __device__ __forceinline__ float leaky(float x) {
    return fmaxf(x, 0.f) + 0.2f * fminf(x, 0.f);
}

// ---------------- K1: h = x@W via fp16 hi/lo 3-pass HMMA, s = h@a_w + ab ---
static constexpr int XP       = 272;
static constexpr int OFF_XHI  = 0;
static constexpr int OFF_XLO  = OFF_XHI + 64 * XP;
static constexpr int OFF_WHI  = OFF_XLO + 64 * XP;
static constexpr int OFF_WLO  = OFF_WHI + 128 * XP;
static constexpr int OFF_AW   = OFF_WLO + 128 * XP;
static constexpr int OFF_SSM  = OFF_AW + 512;
static constexpr int SM1_SIZE = OFF_SSM + 256;

__global__ void __launch_bounds__(256) k_prep(const float* __restrict__ x,
                                              const float* __restrict__ W,
                                              const float* __restrict__ aw,
                                              const float* __restrict__ ab) {
    extern __shared__ char smp[];
    const uint32_t sbp = smem_u32(smp);
    const int tid = threadIdx.x, wid = tid >> 5, lane = tid & 31;
    const int b = blockIdx.x >> 5;
    const int i0 = (blockIdx.x & 31) * 64;

    const float4* xb = (const float4*)(x + ((size_t)b * 2048 + i0) * 128);
#pragma unroll
    for (int k = 0; k < 8; k++) {
        int idx = tid + 256 * k;
        int row = idx >> 5, c4 = idx & 31;
        float4 v = xb[idx];
        __half2 h0 = __floats2half2_rn(v.x, v.y);
        __half2 h1 = __floats2half2_rn(v.z, v.w);
        float2 f0 = __half22float2(h0), f1 = __half22float2(h1);
        __half2 l0 = __floats2half2_rn(v.x - f0.x, v.y - f0.y);
        __half2 l1 = __floats2half2_rn(v.z - f1.x, v.w - f1.y);
        char* d = smp + OFF_XHI + row * XP + c4 * 8;
        *(uint2*)d = make_uint2(*(uint32_t*)&h0, *(uint32_t*)&h1);
        *(uint2*)(d + (OFF_XLO - OFF_XHI)) = make_uint2(*(uint32_t*)&l0, *(uint32_t*)&l1);
    }
    const float4* wb = (const float4*)W;
#pragma unroll
    for (int k = 0; k < 16; k++) {
        int idx = tid + 256 * k;
        int row = idx >> 5, c4 = idx & 31;
        float4 v = wb[idx];
        __half2 h0 = __floats2half2_rn(v.x, v.y);
        __half2 h1 = __floats2half2_rn(v.z, v.w);
        float2 f0 = __half22float2(h0), f1 = __half22float2(h1);
        __half2 l0 = __floats2half2_rn(v.x - f0.x, v.y - f0.y);
        __half2 l1 = __floats2half2_rn(v.z - f1.x, v.w - f1.y);
        char* d = smp + OFF_WHI + row * XP + c4 * 8;
        *(uint2*)d = make_uint2(*(uint32_t*)&h0, *(uint32_t*)&h1);
        *(uint2*)(d + (OFF_WLO - OFF_WHI)) = make_uint2(*(uint32_t*)&l0, *(uint32_t*)&l1);
    }
    if (tid < 128) ((float*)(smp + OFF_AW))[tid] = aw[tid];
    if (tid < 64) ((float*)(smp + OFF_SSM))[tid] = 0.f;
    __syncthreads();

    const int r0 = (wid & 3) * 16, c0 = (wid >> 2) * 64;
    float acc[8][4];
#pragma unroll
    for (int nb = 0; nb < 8; nb++)
#pragma unroll
        for (int q = 0; q < 4; q++) acc[nb][q] = 0.f;

    const uint32_t arow = (uint32_t)((r0 + (lane & 15)) * XP + ((lane >> 4) << 4));
    const uint32_t brow = (uint32_t)((lane & 15) * XP + ((lane >> 4) << 4) + c0 * 2);
#pragma unroll
    for (int kk = 0; kk < 8; kk++) {
        uint32_t aph[4], apl[4];
        ldsm4(aph, sbp + OFF_XHI + arow + kk * 32);
        ldsm4(apl, sbp + OFF_XLO + arow + kk * 32);
        const uint32_t hb = sbp + OFF_WHI + brow + kk * 16 * XP;
#pragma unroll
        for (int n0 = 0; n0 < 4; n0++) {
            uint32_t bh[4], bl[4];
            ldsm4t(bh, hb + n0 * 32);
            ldsm4t(bl, hb + (OFF_WLO - OFF_WHI) + n0 * 32);
            mma16816(acc[2 * n0],     aph, bh[0], bh[1]);
            mma16816(acc[2 * n0 + 1], aph, bh[2], bh[3]);
            mma16816(acc[2 * n0],     apl, bh[0], bh[1]);
            mma16816(acc[2 * n0 + 1], apl, bh[2], bh[3]);
            mma16816(acc[2 * n0],     aph, bl[0], bl[1]);
            mma16816(acc[2 * n0 + 1], aph, bl[2], bl[3]);
        }
    }

    const float* awp = (const float*)(smp + OFF_AW);
    float* ssm = (float*)(smp + OFF_SSM);
    const int row_lo = r0 + (lane >> 2);
    __half* hout0 = g_h_hi + ((size_t)b * 2048 + i0 + row_lo) * 128;
    __half* hout1 = hout0 + 8 * 128;
    float s0 = 0.f, s1 = 0.f;
#pragma unroll
    for (int nb = 0; nb < 8; nb++) {
        const int col = c0 + nb * 8 + (lane & 3) * 2;
        __half2 o0 = __floats2half2_rn(acc[nb][0], acc[nb][1]);
        __half2 o1 = __floats2half2_rn(acc[nb][2], acc[nb][3]);
        *(uint32_t*)(hout0 + col) = *(uint32_t*)&o0;
        *(uint32_t*)(hout1 + col) = *(uint32_t*)&o1;
        s0 += acc[nb][0] * awp[col] + acc[nb][1] * awp[col + 1];
        s1 += acc[nb][2] * awp[col] + acc[nb][3] * awp[col + 1];
    }
    s0 += __shfl_xor_sync(0xffffffffu, s0, 1);
    s0 += __shfl_xor_sync(0xffffffffu, s0, 2);
    s1 += __shfl_xor_sync(0xffffffffu, s1, 1);
    s1 += __shfl_xor_sync(0xffffffffu, s1, 2);
    if ((lane & 3) == 0) {
        atomicAdd(&ssm[row_lo], s0);
        atomicAdd(&ssm[row_lo + 8], s1);
    }
    __syncthreads();
    if (tid < 64) g_s[b * 2048 + i0 + tid] = ssm[tid] + ab[0];
}

// ---------------- K2: R14 base, TWO chunks per barrier interval ------------
// 512 threads: warps 0-7 = MMA (R14 tiling: 4 row-grp x 2 col-grp),
// warps 8-15 = producers. 17 barriers instead of 33.
// P: 4 stages (idx c&3). H: 8 stages (idx c&7).
static constexpr int P_PITCH = 144;
static constexpr int H_PITCH = 272;
static constexpr int P_ST    = 64 * P_PITCH;        // 9216
static constexpr int H_ST    = 64 * H_PITCH;        // 17408
static constexpr int OFF_P   = 0;                   // 4 stages -> 36864
static constexpr int OFF_H   = 4 * P_ST;            // 36864; 8 stages -> 176128
static constexpr int OFF_SS   = OFF_H + 8 * H_ST;   // 176128 (2048 f)
static constexpr int OFF_BIAS = OFF_SS + 8192;      // 184320 (128 f)
static constexpr int OFF_LS   = OFF_BIAS + 512;     // 184832 (64 f)
static constexpr int OFF_SMAX = OFF_LS + 256;       // 185088 (1 f)
static constexpr int SM2_SIZE = OFF_SMAX + 16;      // 185104

__global__ void __launch_bounds__(512) k_attn(const float* __restrict__ A,
                                              const float* __restrict__ bias,
                                              float* __restrict__ out) {
    extern __shared__ char sm[];
    const uint32_t sb = smem_u32(sm);
    const int tid = threadIdx.x, wid = tid >> 5, lane = tid & 31;
    const int b = blockIdx.x >> 5;
    const int i0 = (blockIdx.x & 31) << 6;

    const __half* Hhig = g_h_hi + (size_t)b * 2048 * 128;
    const int p = tid - 256;                 // producer index (valid when wid>=8)
    const int pfc = p & 15, pjrb = p >> 4;

    // preamble: producers issue H(0), H(1)
    if (wid >= 8) {
#pragma unroll
        for (int tc = 0; tc < 2; tc++) {
            const uint32_t bb = sb + OFF_H + tc * H_ST;
#pragma unroll
            for (int c = 0; c < 4; c++) {
                const int jr = pjrb + 16 * c;
                cp16(bb + jr * H_PITCH + pfc * 16,
                     Hhig + (size_t)(tc * 64 + jr) * 128 + pfc * 8);
            }
            cp_commit();
        }
    }

    float* ss = (float*)(sm + OFF_SS);
    {   // preload s for whole batch + bias
        const float4* sg = (const float4*)(g_s + b * 2048);
        ((float4*)ss)[tid] = sg[tid];
        if (tid < 128) ((float*)(sm + OFF_BIAS))[tid] = bias[tid];
    }
    __syncthreads();

    // batch-wide max of s (fp16-safe shift)
    {
        float mx = -1e30f;
#pragma unroll
        for (int k = 0; k < 4; k++) mx = fmaxf(mx, ss[tid + 512 * k]);
#pragma unroll
        for (int off = 16; off >= 1; off >>= 1)
            mx = fmaxf(mx, __shfl_xor_sync(0xffffffffu, mx, off));
        if (lane == 0) ((float*)(sm + OFF_LS))[wid] = mx;
    }
    __syncthreads();
    if (tid == 0) {
        float mx = -1e30f;
#pragma unroll
        for (int w = 0; w < 16; w++) mx = fmaxf(mx, ((float*)(sm + OFF_LS))[w]);
        *(float*)(sm + OFF_SMAX) = mx;
    }
    __syncthreads();
    const float smax = *(const float*)(sm + OFF_SMAX);

    // ---- per-role persistent state ----
    // producer
    const int rbase = p >> 4, cbase = (p & 15) * 4;
    const float* Abase = A + ((size_t)b * 2048 + i0) * 2048;
    float s_i[4], m_i[4], lsum[4];
    float4 av[4];
    // consumer (R14 tiling: 4 row-groups x 2 col-groups)
    const int r0 = (wid & 3) * 16, c0 = (wid >> 2) * 64;
    float acc[8][4];
    const uint32_t arow = (uint32_t)((r0 + (lane & 15)) * P_PITCH + ((lane >> 4) << 4));
    const uint32_t brow = (uint32_t)((lane & 15) * H_PITCH + ((lane >> 4) << 4) + c0 * 2);

    if (wid >= 8) {
#pragma unroll
        for (int it = 0; it < 4; it++) {
            s_i[it] = ss[i0 + rbase + 16 * it];
            m_i[it] = leaky(s_i[it] + smax);
            lsum[it] = 0.f;
        }
#pragma unroll
        for (int it = 0; it < 4; it++)
            av[it] = *(const float4*)(Abase + (size_t)(rbase + 16 * it) * 2048 + cbase);
    } else {
#pragma unroll
        for (int nb = 0; nb < 8; nb++)
#pragma unroll
            for (int q = 0; q < 4; q++) acc[nb][q] = 0.f;
    }

#pragma unroll 1
    for (int tt = 0; tt <= 16; tt++) {
        if (wid >= 8) {
            if (tt < 16) {
#pragma unroll
                for (int d = 0; d < 2; d++) {
                    const int t = 2 * tt + d;        // chunk being produced
                    // prefetch H(t+2)
                    if (t < 30) {
                        const uint32_t bbn = sb + OFF_H + ((t + 2) & 7) * H_ST;
#pragma unroll
                        for (int c = 0; c < 4; c++) {
                            const int jr = pjrb + 16 * c;
                            cp16(bbn + jr * H_PITCH + pfc * 16,
                                 Hhig + (size_t)((t + 2) * 64 + jr) * 128 + pfc * 8);
                        }
                        cp_commit();
                    }
                    // A prefetch t+1
                    const int j0n = (t < 31) ? (t + 1) * 64 : t * 64;
                    float4 avn[4];
#pragma unroll
                    for (int it = 0; it < 4; it++)
                        avn[it] = *(const float4*)(Abase + (size_t)(rbase + 16 * it) * 2048 + j0n + cbase);

                    // P(t) -> stage t&3
                    const int j0 = t * 64;
                    char* bp = sm + OFF_P + (t & 3) * P_ST;
                    const float4 sv = *(const float4*)(ss + j0 + cbase);
#pragma unroll
                    for (int it = 0; it < 4; it++) {
                        const float si = s_i[it], m = m_i[it];
                        float e0 = leaky(si + sv.x) - m;
                        float e1 = leaky(si + sv.y) - m;
                        float e2 = leaky(si + sv.z) - m;
                        float e3 = leaky(si + sv.w) - m;
                        float p0 = __expf(e0 + av[it].x), p1 = __expf(e1 + av[it].y);
                        float p2 = __expf(e2 + av[it].z), p3 = __expf(e3 + av[it].w);
                        lsum[it] += (p0 + p1) + (p2 + p3);
                        __half2 hA = __floats2half2_rn(p0, p1);
                        __half2 hB = __floats2half2_rn(p2, p3);
                        *(uint2*)(bp + (rbase + 16 * it) * P_PITCH + cbase * 2) =
                            make_uint2(*(uint32_t*)&hA, *(uint32_t*)&hB);
                    }
#pragma unroll
                    for (int it = 0; it < 4; it++) av[it] = avn[it];
                }
                // H(2tt), H(2tt+1) must be complete before the barrier
                // (consumer reads them next iteration).
                if (tt <= 14) cp_waitg<2>();   // leaves newest 2 (H(2tt+2..3)) pending
                else          cp_waitg<0>();   // tail: drain all
            }
        } else {
            if (tt >= 1) {
#pragma unroll
                for (int d = 0; d < 2; d++) {
                    const int c = 2 * tt - 2 + d;
                    const uint32_t pb = sb + OFF_P + (c & 3) * P_ST;
                    const uint32_t hb0 = sb + OFF_H + (c & 7) * H_ST;
#pragma unroll
                    for (int kk = 0; kk < 4; kk++) {
                        uint32_t ap[4];
                        ldsm4(ap, pb + arow + kk * 32);
                        const uint32_t hb = hb0 + brow + kk * 16 * H_PITCH;
                        uint32_t bh[4][4];
#pragma unroll
                        for (int n0 = 0; n0 < 4; n0++) ldsm4t(bh[n0], hb + n0 * 32);
#pragma unroll
                        for (int n0 = 0; n0 < 4; n0++) {
                            mma16816(acc[2 * n0],     ap, bh[n0][0], bh[n0][1]);
                            mma16816(acc[2 * n0 + 1], ap, bh[n0][2], bh[n0][3]);
                        }
                    }
                }
            }
        }
        __syncthreads();
    }

    // producers publish per-row sums
    if (wid >= 8) {
        float* ls = (float*)(sm + OFF_LS);
#pragma unroll
        for (int it = 0; it < 4; it++) {
            float v = lsum[it];
            v += __shfl_xor_sync(0xffffffffu, v, 1);
            v += __shfl_xor_sync(0xffffffffu, v, 2);
            v += __shfl_xor_sync(0xffffffffu, v, 4);
            v += __shfl_xor_sync(0xffffffffu, v, 8);
            if ((p & 15) == 0) ls[rbase + 16 * it] = v;
        }
    }
    __syncthreads();

    if (wid < 8) {
        const float* ls = (const float*)(sm + OFF_LS);
        const float* bs = (const float*)(sm + OFF_BIAS);
        const int row_lo = r0 + (lane >> 2);
        const float linv0 = 1.0f / ls[row_lo];
        const float linv1 = 1.0f / ls[row_lo + 8];
        float* orow0 = out + ((size_t)b * 2048 + i0 + row_lo) * 128;
        float* orow1 = orow0 + 8 * 128;
#pragma unroll
        for (int nb = 0; nb < 8; nb++) {
            const int col = c0 + nb * 8 + (lane & 3) * 2;
            float2 o0 = make_float2(acc[nb][0] * linv0 + bs[col],
                                    acc[nb][1] * linv0 + bs[col + 1]);
            float2 o1 = make_float2(acc[nb][2] * linv1 + bs[col],
                                    acc[nb][3] * linv1 + bs[col + 1]);
            *(float2*)(orow0 + col) = o0;
            *(float2*)(orow1 + col) = o1;
        }
    }
}

extern "C" void kernel_launch(void* const* d_in, const int* in_sizes, int n_in,
                              void* d_out, int out_size) {
    (void)in_sizes; (void)n_in; (void)out_size;
    const float* x    = (const float*)d_in[0];
    const float* A    = (const float*)d_in[1];
    const float* W    = (const float*)d_in[2];
    const float* aw   = (const float*)d_in[3];
    const float* ab   = (const float*)d_in[4];
    const float* bias = (const float*)d_in[5];
    float* out = (float*)d_out;

    cudaFuncSetAttribute(k_prep, cudaFuncAttributeMaxDynamicSharedMemorySize, SM1_SIZE);
    cudaFuncSetAttribute(k_attn, cudaFuncAttributeMaxDynamicSharedMemorySize, SM2_SIZE);

    k_prep<<<128, 256, SM1_SIZE>>>(x, W, aw, ab);
    k_attn<<<128, 512, SM2_SIZE>>>(A, bias, out);
}